// round 9
// baseline (speedup 1.0000x reference)
#include <cuda_runtime.h>
#include <math.h>
#include <cstdint>

#define HID   2048
#define INTER 8192
#define QKV   8192
#define TV    4096
#define NVH   32
#define KD    128
#define VD    128
#define NKH   16
#define PROJ_ROWS (QKV + TV + 2 * NVH)   // 12352

#define MODE_PLAIN  0
#define MODE_ATOMIC 1
#define MODE_GATEUP 2

#define TILE_BYTES 16384
#define ROW_BYTES  8192
#define NB 592               // total blocks, 4 per SM, all co-resident

// ---- scratch ----
__device__ float g_proj[PROJ_ROWS];
__device__ float g_yg[TV];
__device__ float g_x1[HID];
__device__ float g_act[INTER];
__device__ unsigned g_cnt[4];

__device__ __forceinline__ float warp_sum(float v) {
#pragma unroll
    for (int o = 16; o; o >>= 1) v += __shfl_xor_sync(0xffffffffu, v, o);
    return v;
}
__device__ __forceinline__ unsigned smem_u32(const void* p) {
    return (unsigned)__cvta_generic_to_shared(p);
}
__device__ __forceinline__ void mbar_init(unsigned a, unsigned cnt) {
    asm volatile("mbarrier.init.shared.b64 [%0], %1;" :: "r"(a), "r"(cnt) : "memory");
}
__device__ __forceinline__ void mbar_expect(unsigned a, unsigned bytes) {
    asm volatile("mbarrier.arrive.expect_tx.shared.b64 _, [%0], %1;"
                 :: "r"(a), "r"(bytes) : "memory");
}
__device__ __forceinline__ void bulk_g2s(unsigned dst, const void* src, unsigned bytes,
                                         unsigned mbar) {
    asm volatile("cp.async.bulk.shared::cta.global.mbarrier::complete_tx::bytes "
                 "[%0], [%1], %2, [%3];"
                 :: "r"(dst), "l"(src), "r"(bytes), "r"(mbar) : "memory");
}
__device__ __forceinline__ void mbar_wait(unsigned a, unsigned phase) {
    asm volatile("{\n\t"
                 ".reg .pred P;\n\t"
                 "WAIT_%=:\n\t"
                 "mbarrier.try_wait.parity.acquire.cta.shared::cta.b64 P, [%0], %1;\n\t"
                 "@P bra DONE_%=;\n\t"
                 "bra WAIT_%=;\n\t"
                 "DONE_%=:\n\t"
                 "}" :: "r"(a), "r"(phase) : "memory");
}
__device__ __forceinline__ void fence_async() {
    asm volatile("fence.proxy.async.shared::cta;" ::: "memory");
}

// grid-wide barrier; all NB blocks resident by construction
__device__ __forceinline__ void grid_bar(int id) {
    __syncthreads();
    if (threadIdx.x == 0) {
        __threadfence();
        atomicAdd(&g_cnt[id], 1u);
        while (*((volatile unsigned*)&g_cnt[id]) < NB) { }
        __threadfence();
    }
    __syncthreads();
}

// one 16KB tile = 2 x 8KB bulk copies
__device__ __forceinline__ void issue_tile(int tid, unsigned mb, float4* dst4,
        const float* W, const float* W2, size_t cb, int strideK, int T) {
    if (tid != 0) return;
    unsigned dst = smem_u32(dst4);
    mbar_expect(mb, TILE_BYTES);
    if (W2) {
        bulk_g2s(dst,             W  + (size_t)T * strideK + cb, ROW_BYTES, mb);
        bulk_g2s(dst + ROW_BYTES, W2 + (size_t)T * strideK + cb, ROW_BYTES, mb);
    } else {
        bulk_g2s(dst,             W + (size_t)(2 * T)     * strideK + cb, ROW_BYTES, mb);
        bulk_g2s(dst + ROW_BYTES, W + (size_t)(2 * T + 1) * strideK + cb, ROW_BYTES, mb);
    }
}

// ---- one GEMV stage over the persistent ring (KC = 2048 fixed) ----
// Assumes `preloaded` tiles of this stage already issued. At the end issues
// `npre` tiles of the next stage (nW...) so DRAM streams across the barrier.
template <int MODE, bool LN>
__device__ void gemv_stage(int tid,
        const unsigned* mb, unsigned& phbits, unsigned& icnt, unsigned& wcnt,
        float4* sx4, float4* bufb, float* sacc, float* sred,
        const float* W, const float* W2, size_t cb, int strideK,
        const float* xsrc, const float* lnw, float* outv, float* xcopy,
        int t0, int tstr, int NT, int preloaded,
        const float* nW, const float* nW2, size_t ncb, int nstrideK,
        int nt0, int ntstr, int npre) {
    float* sx = reinterpret_cast<float*>(sx4);
    // ---- stage x ----
    if (LN) {
        float s = 0.f;
        for (int i = tid; i < 2048; i += 256) {
            float v = xsrc[i];
            sx[i] = v;
            if (xcopy) xcopy[i] = v;
            s += v * v;
        }
        s = warp_sum(s);
        if ((tid & 31) == 0) sred[tid >> 5] = s;
        __syncthreads();
        if (tid < 32) {
            float v = (tid < 8) ? sred[tid] : 0.f;
            v = warp_sum(v);
            if (tid == 0) sred[8] = rsqrtf(v / 2048.f + 1e-6f);
        }
        __syncthreads();
        float inv = sred[8];
        for (int i = tid; i < 2048; i += 256)
            sx[i] = sx[i] * inv * (1.f + lnw[i]);
        __syncthreads();
    } else {
        for (int i = tid; i < 2048; i += 256) sx[i] = xsrc[i];
        __syncthreads();
    }
    const int w = tid >> 5, lane = tid & 31;
    const int rl = w >> 2, q = w & 3;
    float4 xr[4];
#pragma unroll
    for (int j = 0; j < 4; j++) xr[j] = sx4[q * 128 + j * 32 + lane];

    const int cnt = (NT - t0 + tstr - 1) / tstr;
    int toIssue = preloaded;
    for (int idx = 0; idx < cnt; idx++) {
        while (toIssue <= idx + 1 && toIssue < cnt) {
            issue_tile(tid, mb[icnt & 1], bufb + (icnt & 1) * 1024,
                       W, W2, cb, strideK, t0 + toIssue * tstr);
            icnt++; toIssue++;
        }
        const int s = wcnt & 1; wcnt++;
        mbar_wait(mb[s], (phbits >> s) & 1);
        phbits ^= (1u << s);
        const int par = idx & 1;
        {
            const float4* src = bufb + s * 1024 + rl * 512;
            float acc = 0.f;
#pragma unroll
            for (int j = 0; j < 4; j++) {
                float4 wv = src[q * 128 + j * 32 + lane];
                acc += wv.x * xr[j].x + wv.y * xr[j].y + wv.z * xr[j].z + wv.w * xr[j].w;
            }
            acc = warp_sum(acc);
            if (lane == 0) sacc[par * 8 + rl * 4 + q] = acc;
        }
        __syncthreads();
        const int T = t0 + idx * tstr;
        if (MODE == MODE_PLAIN) {
            if (tid < 2) {
                const float* a = &sacc[par * 8 + tid * 4];
                outv[2 * T + tid] = a[0] + a[1] + a[2] + a[3];
            }
        } else if (MODE == MODE_ATOMIC) {
            if (tid < 2) {
                const float* a = &sacc[par * 8 + tid * 4];
                atomicAdd(&outv[2 * T + tid], a[0] + a[1] + a[2] + a[3]);
            }
        } else {
            if (tid == 0) {
                const float* a0 = &sacc[par * 8];
                const float* a1 = &sacc[par * 8 + 4];
                float ag = a0[0] + a0[1] + a0[2] + a0[3];
                float au = a1[0] + a1[1] + a1[2] + a1[3];
                outv[T] = (ag / (1.f + expf(-ag))) * au;
            }
        }
    }
    // preload next stage's first tiles (weights are data-independent)
    for (int j = 0; j < npre; j++) {
        issue_tile(tid, mb[icnt & 1], bufb + (icnt & 1) * 1024,
                   nW, nW2, ncb, nstrideK, nt0 + j * ntstr);
        icnt++;
    }
}

// ================= the whole layer, one persistent kernel =================
__global__ void __launch_bounds__(256, 4)
fused_all(const float* __restrict__ x, const float* __restrict__ cs,
          const float* __restrict__ S, const float* __restrict__ in_ln_w,
          const float* __restrict__ in_proj_w, const float* __restrict__ cw,
          const float* __restrict__ A_log, const float* __restrict__ dt_bias,
          const float* __restrict__ norm_w, const float* __restrict__ out_proj_w,
          const float* __restrict__ post_ln_w, const float* __restrict__ gate_w,
          const float* __restrict__ up_w, const float* __restrict__ down_w,
          float* out_x, float* out_cs, float* out_ssm,
          float* proj, float* yg, float* x1, float* act) {
    extern __shared__ __align__(128) float4 dyn[];
    float4* sx4  = dyn;            // 512 float4 = 8KB
    float4* bufb = dyn + 512;      // 2048 float4 = 32KB (2 tiles)
    __shared__ float sacc[16];
    __shared__ float sred[9];
    __shared__ __align__(8) unsigned long long mbar_s[2];
    __shared__ float d_sq[KD], d_sk[KD], d_sv[VD], d_sdelta[VD], d_spart[2][VD], d_sred[8];

    const int tid = threadIdx.x;
    const int bid = blockIdx.x;
    unsigned mb[2] = { smem_u32(&mbar_s[0]), smem_u32(&mbar_s[1]) };
    if (tid == 0) { mbar_init(mb[0], 1); mbar_init(mb[1], 1); fence_async(); }
    __syncthreads();

    unsigned phbits = 0, icnt = 0, wcnt = 0;

    // ---- preload stage A tiles 0,1 (overlaps LN staging) ----
    issue_tile(tid, mb[icnt & 1], bufb + (icnt & 1) * 1024, in_proj_w, nullptr, 0, HID, bid); icnt++;
    issue_tile(tid, mb[icnt & 1], bufb + (icnt & 1) * 1024, in_proj_w, nullptr, 0, HID, bid + NB); icnt++;

    // ---- Stage A: in_proj (12352x2048), fused input rmsnorm; block0 seeds x1=x ----
    // next = stage C (out_proj split-2)
    const int c_t0 = bid >> 1;
    const size_t c_cb = (size_t)(bid & 1) * 2048;
    gemv_stage<MODE_PLAIN, true>(tid, mb, phbits, icnt, wcnt, sx4, bufb, sacc, sred,
        in_proj_w, nullptr, 0, HID,
        x, in_ln_w, proj, (bid == 0) ? x1 : nullptr,
        bid, NB, PROJ_ROWS / 2, 2,
        out_proj_w, nullptr, c_cb, TV, c_t0, 296, 2);

    grid_bar(0);

    // ---- Stage B: conv + gated delta rule (blocks 0..31, one head each) ----
    if (bid < NVH) {
        const int h = bid, t = tid & (VD - 1), p = tid >> 7, kh = h >> 1;
        for (int rr = tid; rr < 384; rr += 256) {
            int row;
            if (rr < 128)      row = kh * KD + rr;
            else if (rr < 256) row = NKH * KD + kh * KD + (rr - 128);
            else               row = 2 * NKH * KD + h * VD + (rr - 256);
            float4 c = __ldg(reinterpret_cast<const float4*>(cs) + row);
            float4 wv = __ldg(reinterpret_cast<const float4*>(cw) + row);
            float qv = proj[row];
            float s = c.y * wv.x + c.z * wv.y + c.w * wv.z + qv * wv.w;
            float a = s / (1.f + expf(-s));
            if (rr < 128)      d_sq[rr] = a;
            else if (rr < 256) d_sk[rr - 128] = a;
            else               d_sv[rr - 256] = a;
            if (rr >= 256 || (h & 1) == 0)
                reinterpret_cast<float4*>(out_cs)[row] = make_float4(c.y, c.z, c.w, qv);
        }
        __syncthreads();
        {
            float v = (tid < 128) ? d_sq[tid] : d_sk[tid - 128];
            float ss = warp_sum(v * v);
            if ((tid & 31) == 0) d_sred[tid >> 5] = ss;
        }
        __syncthreads();
        float sumq = d_sred[0] + d_sred[1] + d_sred[2] + d_sred[3];
        float sumk = d_sred[4] + d_sred[5] + d_sred[6] + d_sred[7];
        float inq = 1.f / fmaxf(sqrtf(sumq), 1e-12f);
        float ink = 1.f / fmaxf(sqrtf(sumk), 1e-12f);

        float ar = proj[QKV + TV + h];
        float br = proj[QKV + TV + NVH + h];
        float beta = 1.f / (1.f + expf(-br));
        float xsp = ar + dt_bias[h];
        float sp = (xsp > 20.f) ? xsp : log1pf(expf(xsp));
        float decay = expf(-expf(A_log[h]) * sp);

        const float* Sh = S + (size_t)h * KD * VD;
        float* So = out_ssm + (size_t)h * KD * VD;

        float acc = 0.f;
#pragma unroll 8
        for (int j = 0; j < 64; j++) {
            int k = p * 64 + j;
            acc += Sh[k * VD + t] * d_sk[k];
        }
        d_spart[p][t] = acc * ink;
        __syncthreads();
        if (p == 0) d_sdelta[t] = d_sv[t] - (d_spart[0][t] + d_spart[1][t]);
        __syncthreads();
        float d = d_sdelta[t];
        float y = 0.f;
#pragma unroll 8
        for (int j = 0; j < 64; j++) {
            int k = p * 64 + j;
            float ns = decay * Sh[k * VD + t] + beta * (d_sk[k] * ink) * d;
            So[k * VD + t] = ns;
            y += ns * d_sq[k];
        }
        d_spart[p][t] = y * inq;
        __syncthreads();
        float yy = 0.f;
        if (tid < VD) {
            yy = d_spart[0][tid] + d_spart[1][tid];
            float vy = warp_sum(yy * yy);
            if ((tid & 31) == 0) d_sred[tid >> 5] = vy;
        }
        __syncthreads();
        if (tid < VD) {
            float sumy = d_sred[0] + d_sred[1] + d_sred[2] + d_sred[3];
            float yn = yy * rsqrtf(sumy / (float)VD + 1e-6f) * norm_w[tid];
            float z = proj[QKV + h * VD + tid];
            yg[h * VD + tid] = yn * (z / (1.f + expf(-z)));
        }
    }

    grid_bar(1);

    // ---- Stage C: out_proj (2048x4096) split-2, atomics onto x1 ----
    // next = stage D (gateup)
    gemv_stage<MODE_ATOMIC, false>(tid, mb, phbits, icnt, wcnt, sx4, bufb, sacc, sred,
        out_proj_w, nullptr, c_cb, TV,
        yg + c_cb, nullptr, x1, nullptr,
        c_t0, 296, HID / 2, 2,
        gate_w, up_w, 0, HID, bid, NB, 2);

    grid_bar(2);

    // ---- Stage D: post-rmsnorm + gate/up + SwiGLU; block0 seeds out_x=x1 ----
    // next = stage E (down split-4)
    const int e_t0 = bid >> 2;
    const size_t e_cb = (size_t)(bid & 3) * 2048;
    gemv_stage<MODE_GATEUP, true>(tid, mb, phbits, icnt, wcnt, sx4, bufb, sacc, sred,
        gate_w, up_w, 0, HID,
        x1, post_ln_w, act, (bid == 0) ? out_x : nullptr,
        bid, NB, INTER, 2,
        down_w, nullptr, e_cb, INTER, e_t0, 148, 2);

    grid_bar(3);

    // ---- Stage E: down (2048x8192) split-4, atomics onto out_x ----
    gemv_stage<MODE_ATOMIC, false>(tid, mb, phbits, icnt, wcnt, sx4, bufb, sacc, sred,
        down_w, nullptr, e_cb, INTER,
        act + e_cb, nullptr, out_x, nullptr,
        e_t0, 148, HID / 2, 2,
        nullptr, nullptr, 0, 0, 0, 0, 0);
}

__global__ void reset_k() {
    if (threadIdx.x < 4) g_cnt[threadIdx.x] = 0;
}

extern "C" void kernel_launch(void* const* d_in, const int* in_sizes, int n_in,
                              void* d_out, int out_size) {
    const float* x          = (const float*)d_in[0];
    const float* conv_state = (const float*)d_in[1];
    const float* ssm_state  = (const float*)d_in[2];
    const float* in_ln_w    = (const float*)d_in[3];
    const float* in_proj_w  = (const float*)d_in[4];
    const float* conv_w     = (const float*)d_in[5];
    const float* A_log      = (const float*)d_in[6];
    const float* dt_bias    = (const float*)d_in[7];
    const float* norm_w     = (const float*)d_in[8];
    const float* out_proj_w = (const float*)d_in[9];
    const float* post_ln_w  = (const float*)d_in[10];
    const float* gate_w     = (const float*)d_in[11];
    const float* up_w       = (const float*)d_in[12];
    const float* down_w     = (const float*)d_in[13];

    float* out = (float*)d_out;
    float* out_x    = out;
    float* out_conv = out + HID;
    float* out_ssm  = out + HID + QKV * 4;

    float *p_proj, *p_yg, *p_x1, *p_act;
    cudaGetSymbolAddress((void**)&p_proj, g_proj);
    cudaGetSymbolAddress((void**)&p_yg,   g_yg);
    cudaGetSymbolAddress((void**)&p_x1,   g_x1);
    cudaGetSymbolAddress((void**)&p_act,  g_act);

    const size_t dsm = (512 + 2048) * sizeof(float4);   // 40 KB

    reset_k<<<1, 32>>>();
    fused_all<<<NB, 256, dsm>>>(
        x, conv_state, ssm_state, in_ln_w, in_proj_w, conv_w, A_log, dt_bias,
        norm_w, out_proj_w, post_ln_w, gate_w, up_w, down_w,
        out_x, out_conv, out_ssm, p_proj, p_yg, p_x1, p_act);
}

// round 10
// speedup vs baseline: 1.0056x; 1.0056x over previous
#include <cuda_runtime.h>
#include <math.h>
#include <cstdint>

#define HID   2048
#define INTER 8192
#define QKV   8192
#define TV    4096
#define NVH   32
#define KD    128
#define VD    128
#define NKH   16
#define PROJ_ROWS (QKV + TV + 2 * NVH)   // 12352

#define MODE_PLAIN  0
#define MODE_ATOMIC 1
#define MODE_GATEUP 2

#define NBUF 3               // mbarrier ring depth (16KB tiles)
#define TILE_BYTES 16384
#define ROW_BYTES  8192

// ---- scratch ----
__device__ float g_proj[PROJ_ROWS];
__device__ float g_yg[TV];
__device__ float g_x1[HID];
__device__ float g_act[INTER];

__device__ __forceinline__ float warp_sum(float v) {
#pragma unroll
    for (int o = 16; o; o >>= 1) v += __shfl_xor_sync(0xffffffffu, v, o);
    return v;
}
__device__ __forceinline__ unsigned smem_u32(const void* p) {
    return (unsigned)__cvta_generic_to_shared(p);
}
__device__ __forceinline__ void mbar_init(unsigned a, unsigned cnt) {
    asm volatile("mbarrier.init.shared.b64 [%0], %1;" :: "r"(a), "r"(cnt) : "memory");
}
__device__ __forceinline__ void mbar_expect(unsigned a, unsigned bytes) {
    asm volatile("mbarrier.arrive.expect_tx.shared.b64 _, [%0], %1;"
                 :: "r"(a), "r"(bytes) : "memory");
}
__device__ __forceinline__ uint64_t l2_evict_first_policy() {
    uint64_t pol;
    asm("createpolicy.fractional.L2::evict_first.b64 %0, 1.0;" : "=l"(pol));
    return pol;
}
__device__ __forceinline__ void bulk_g2s(unsigned dst, const void* src, unsigned bytes,
                                         unsigned mbar, uint64_t pol) {
    asm volatile("cp.async.bulk.shared::cta.global.mbarrier::complete_tx::bytes"
                 ".L2::cache_hint [%0], [%1], %2, [%3], %4;"
                 :: "r"(dst), "l"(src), "r"(bytes), "r"(mbar), "l"(pol) : "memory");
}
__device__ __forceinline__ void mbar_wait(unsigned a, unsigned phase) {
    asm volatile("{\n\t"
                 ".reg .pred P;\n\t"
                 "WAIT_%=:\n\t"
                 "mbarrier.try_wait.parity.acquire.cta.shared::cta.b64 P, [%0], %1;\n\t"
                 "@P bra DONE_%=;\n\t"
                 "bra WAIT_%=;\n\t"
                 "DONE_%=:\n\t"
                 "}" :: "r"(a), "r"(phase) : "memory");
}
__device__ __forceinline__ void fence_async() {
    asm volatile("fence.proxy.async.shared::cta;" ::: "memory");
}

// ================= bulk-copy pipelined GEMV, blocked-contiguous tiles =================
// 256 threads. dyn smem = sx (KC floats) + NBUF 16KB tile buffers.
// Tile = 2 rows (PLAIN/ATOMIC: rows 2T,2T+1 of K-chunk) or {gate T, up T}.
// Block bx owns contiguous tiles [NT*bx/gx, NT*(bx+1)/gx) -> sequential DRAM stream.
// All weight traffic tagged L2::evict_first (read-once, don't thrash L2).
template <int KC, int MODE, bool LN>
__global__ void __launch_bounds__(256)
gemv_bulk(const float* __restrict__ W, const float* __restrict__ W2,
          const float* __restrict__ xin, const float* __restrict__ lnw,
          float* __restrict__ outv, float* __restrict__ xcopy,
          int rows, int strideK) {
    extern __shared__ __align__(128) float4 dyn[];
    float4* sx4  = dyn;                    // KC/4 float4
    float4* bufb = dyn + KC / 4;           // NBUF * 1024 float4
    float* sx = reinterpret_cast<float*>(sx4);
    __shared__ float sacc[2][2][4];        // [parity][row][quarter]
    __shared__ float sred[9];
    __shared__ __align__(8) unsigned long long mbar[NBUF];
    const int tid = threadIdx.x;

    unsigned mb_u32[NBUF];
#pragma unroll
    for (int d = 0; d < NBUF; d++) mb_u32[d] = smem_u32(&mbar[d]);
    const uint64_t pol = l2_evict_first_policy();

    if (tid == 0) {
#pragma unroll
        for (int d = 0; d < NBUF; d++) mbar_init(mb_u32[d], 1);
        fence_async();
    }
    __syncthreads();

    const size_t cb = (size_t)blockIdx.y * KC;
    const int NTtot = (MODE == MODE_GATEUP) ? rows : (rows >> 1);
    const int T0 = (int)(((long long)NTtot * blockIdx.x) / gridDim.x);
    const int T1 = (int)(((long long)NTtot * (blockIdx.x + 1)) / gridDim.x);
    const int cnt = T1 - T0;

    auto issue = [&](int T, int slot) {
        unsigned dst = smem_u32(&bufb[slot * 1024]);
        mbar_expect(mb_u32[slot], TILE_BYTES);
        if (MODE == MODE_GATEUP) {
            bulk_g2s(dst,             W  + (size_t)T * strideK, ROW_BYTES, mb_u32[slot], pol);
            bulk_g2s(dst + ROW_BYTES, W2 + (size_t)T * strideK, ROW_BYTES, mb_u32[slot], pol);
        } else {
            bulk_g2s(dst,             W + (size_t)(2 * T)     * strideK + cb, ROW_BYTES, mb_u32[slot], pol);
            bulk_g2s(dst + ROW_BYTES, W + (size_t)(2 * T + 1) * strideK + cb, ROW_BYTES, mb_u32[slot], pol);
        }
    };

    // prologue: fill the ring (overlaps x staging below)
    if (tid == 0) {
#pragma unroll
        for (int d = 0; d < NBUF; d++)
            if (d < cnt) issue(T0 + d, d);
    }

    // ---- stage x (optionally rmsnorm'd) ----
    if (LN) {
        float s = 0.f;
        bool cp = (xcopy != nullptr) && (blockIdx.x == 0) && (blockIdx.y == 0);
        for (int i = tid; i < KC; i += 256) {
            float v = xin[i];
            sx[i] = v;
            if (cp) xcopy[i] = v;
            s += v * v;
        }
        s = warp_sum(s);
        if ((tid & 31) == 0) sred[tid >> 5] = s;
        __syncthreads();
        if (tid < 32) {
            float v = (tid < 8) ? sred[tid] : 0.f;
            v = warp_sum(v);
            if (tid == 0) sred[8] = rsqrtf(v / (float)KC + 1e-6f);
        }
        __syncthreads();
        float inv = sred[8];
        for (int i = tid; i < KC; i += 256)
            sx[i] = sx[i] * inv * (1.f + lnw[i]);
        __syncthreads();
    } else {
        const float* xc = xin + (size_t)blockIdx.y * KC;
        for (int i = tid; i < KC; i += 256) sx[i] = xc[i];
        __syncthreads();
    }

    const int w = tid >> 5, lane = tid & 31;
    const int rl = w >> 2, q = w & 3;
    float4 xr[4];
#pragma unroll
    for (int j = 0; j < 4; j++) xr[j] = sx4[q * (KC / 16) + j * 32 + lane];

    for (int it = 0; it < cnt; it++) {
        const int slot = it % NBUF;
        const int ph = (it / NBUF) & 1;
        const int par = it & 1;
        const int Tc = T0 + it;
        mbar_wait(mb_u32[slot], ph);
        {
            const float4* src = &bufb[slot * 1024 + rl * 512];
            float acc = 0.f;
#pragma unroll
            for (int j = 0; j < 4; j++) {
                float4 wv = src[q * (KC / 16) + j * 32 + lane];
                acc += wv.x * xr[j].x + wv.y * xr[j].y + wv.z * xr[j].z + wv.w * xr[j].w;
            }
            acc = warp_sum(acc);
            if (lane == 0) sacc[par][rl][q] = acc;
        }
        __syncthreads();   // sacc visible; tile fully consumed
        if (tid == 0 && it + NBUF < cnt) issue(T0 + it + NBUF, slot);
        if (MODE == MODE_PLAIN) {
            if (tid < 2) {
                const float* a = sacc[par][tid];
                outv[2 * Tc + tid] = a[0] + a[1] + a[2] + a[3];
            }
        } else if (MODE == MODE_ATOMIC) {
            if (tid < 2) {
                const float* a = sacc[par][tid];
                atomicAdd(&outv[2 * Tc + tid], a[0] + a[1] + a[2] + a[3]);
            }
        } else {
            if (tid == 0) {
                const float* a0 = sacc[par][0];
                const float* a1 = sacc[par][1];
                float ag = a0[0] + a0[1] + a0[2] + a0[3];
                float au = a1[0] + a1[1] + a1[2] + a1[3];
                float silu = ag / (1.f + expf(-ag));
                outv[Tc] = silu * au;
            }
        }
    }
}

// ================= gated delta rule with fused conv update =================
__global__ void __launch_bounds__(1024, 1)
delta_k(const float* __restrict__ S, const float* __restrict__ proj,
        const float* __restrict__ cs, const float* __restrict__ cw,
        const float* __restrict__ A_log, const float* __restrict__ dt_bias,
        const float* __restrict__ norm_w,
        float* __restrict__ Sout, float* __restrict__ out_cs, float* __restrict__ yg) {
    __shared__ float sq[KD], sk[KD], sv[VD], sdelta[VD], sred[8];
    __shared__ float spart[8][VD];
    int h = blockIdx.x;
    int tid = threadIdx.x;
    int t = tid & (VD - 1);
    int p = tid >> 7;
    int kh = h >> 1;

    if (tid < 384) {
        int row;
        if (tid < 128)      row = kh * KD + tid;
        else if (tid < 256) row = NKH * KD + kh * KD + (tid - 128);
        else                row = 2 * NKH * KD + h * VD + (tid - 256);
        float4 c = __ldg(reinterpret_cast<const float4*>(cs) + row);
        float4 w = __ldg(reinterpret_cast<const float4*>(cw) + row);
        float qv = proj[row];
        float s = c.y * w.x + c.z * w.y + c.w * w.z + qv * w.w;
        float act = s / (1.f + expf(-s));
        if (tid < 128)      sq[tid] = act;
        else if (tid < 256) sk[tid - 128] = act;
        else                sv[tid - 256] = act;
        if (tid >= 256 || (h & 1) == 0)
            reinterpret_cast<float4*>(out_cs)[row] = make_float4(c.y, c.z, c.w, qv);
    }
    __syncthreads();

    if (tid < 256) {
        float v = (tid < 128) ? sq[tid] : sk[tid - 128];
        float ss = warp_sum(v * v);
        if ((tid & 31) == 0) sred[tid >> 5] = ss;
    }
    __syncthreads();
    float sumq = sred[0] + sred[1] + sred[2] + sred[3];
    float sumk = sred[4] + sred[5] + sred[6] + sred[7];
    float inq = 1.f / fmaxf(sqrtf(sumq), 1e-12f);
    float ink = 1.f / fmaxf(sqrtf(sumk), 1e-12f);

    float a = proj[QKV + TV + h];
    float bb = proj[QKV + TV + NVH + h];
    float beta = 1.f / (1.f + expf(-bb));
    float xsp = a + dt_bias[h];
    float sp = (xsp > 20.f) ? xsp : log1pf(expf(xsp));
    float decay = expf(-expf(A_log[h]) * sp);

    const float* Sh = S + (size_t)h * KD * VD;
    float* So = Sout + (size_t)h * KD * VD;

    float Sreg[16];
    float acc = 0.f;
#pragma unroll
    for (int j = 0; j < 16; j++) {
        int k = p * 16 + j;
        Sreg[j] = Sh[k * VD + t];
        acc += Sreg[j] * sk[k];
    }
    spart[p][t] = acc * ink;
    __syncthreads();
    if (p == 0) {
        float s = 0.f;
#pragma unroll
        for (int j = 0; j < 8; j++) s += spart[j][t];
        sdelta[t] = sv[t] - s;
    }
    __syncthreads();

    float d = sdelta[t];
    float yacc = 0.f;
#pragma unroll
    for (int j = 0; j < 16; j++) {
        int k = p * 16 + j;
        float ns = decay * Sreg[j] + beta * (sk[k] * ink) * d;
        So[k * VD + t] = ns;
        yacc += ns * sq[k];
    }
    spart[p][t] = yacc * inq;
    __syncthreads();

    float y = 0.f;
    if (tid < VD) {
#pragma unroll
        for (int j = 0; j < 8; j++) y += spart[j][tid];
        float vy = warp_sum(y * y);
        if ((tid & 31) == 0) sred[tid >> 5] = vy;
    }
    __syncthreads();
    if (tid < VD) {
        float sumy = sred[0] + sred[1] + sred[2] + sred[3];
        float yn = y * rsqrtf(sumy / (float)VD + 1e-6f) * norm_w[tid];
        float z = proj[QKV + h * VD + tid];
        yg[h * VD + tid] = yn * (z / (1.f + expf(-z)));
    }
}

extern "C" void kernel_launch(void* const* d_in, const int* in_sizes, int n_in,
                              void* d_out, int out_size) {
    const float* x          = (const float*)d_in[0];
    const float* conv_state = (const float*)d_in[1];
    const float* ssm_state  = (const float*)d_in[2];
    const float* in_ln_w    = (const float*)d_in[3];
    const float* in_proj_w  = (const float*)d_in[4];
    const float* conv_w     = (const float*)d_in[5];
    const float* A_log      = (const float*)d_in[6];
    const float* dt_bias    = (const float*)d_in[7];
    const float* norm_w     = (const float*)d_in[8];
    const float* out_proj_w = (const float*)d_in[9];
    const float* post_ln_w  = (const float*)d_in[10];
    const float* gate_w     = (const float*)d_in[11];
    const float* up_w       = (const float*)d_in[12];
    const float* down_w     = (const float*)d_in[13];

    float* out = (float*)d_out;
    float* out_x    = out;
    float* out_conv = out + HID;
    float* out_ssm  = out + HID + QKV * 4;

    float *p_proj, *p_yg, *p_x1, *p_act;
    cudaGetSymbolAddress((void**)&p_proj, g_proj);
    cudaGetSymbolAddress((void**)&p_yg,   g_yg);
    cudaGetSymbolAddress((void**)&p_x1,   g_x1);
    cudaGetSymbolAddress((void**)&p_act,  g_act);

    const size_t dsm = (size_t)(HID / 4 + NBUF * 1024) * sizeof(float4);  // 56KB
    static bool attr_done = false;
    cudaFuncSetAttribute(gemv_bulk<HID, MODE_PLAIN,  true>,
                         cudaFuncAttributeMaxDynamicSharedMemorySize, (int)dsm);
    cudaFuncSetAttribute(gemv_bulk<HID, MODE_ATOMIC, false>,
                         cudaFuncAttributeMaxDynamicSharedMemorySize, (int)dsm);
    cudaFuncSetAttribute(gemv_bulk<HID, MODE_GATEUP, true>,
                         cudaFuncAttributeMaxDynamicSharedMemorySize, (int)dsm);
    (void)attr_done;

    // 1. in_proj (fused input rmsnorm; block0 seeds x1 = x): 12352 x 2048
    gemv_bulk<HID, MODE_PLAIN, true><<<592, 256, dsm>>>(
        in_proj_w, nullptr, x, in_ln_w, p_proj, p_x1, PROJ_ROWS, HID);
    // 2. gated delta rule + fused conv; writes new_conv_state and new_ssm_state
    delta_k<<<NVH, 1024>>>(ssm_state, p_proj, conv_state, conv_w,
                           A_log, dt_bias, norm_w, out_ssm, out_conv, p_yg);
    // 3. out_proj split-2, accumulates onto x1: 2048 x 4096
    gemv_bulk<HID, MODE_ATOMIC, false><<<dim3(296, 2), 256, dsm>>>(
        out_proj_w, nullptr, p_yg, nullptr, p_x1, nullptr, HID, TV);
    // 4. fused post-rmsnorm + gate/up + SwiGLU; block0 seeds out_x = x1
    gemv_bulk<HID, MODE_GATEUP, true><<<592, 256, dsm>>>(
        gate_w, up_w, p_x1, post_ln_w, p_act, out_x, INTER, HID);
    // 5. down split-4, accumulates onto out_x: 2048 x 8192
    gemv_bulk<HID, MODE_ATOMIC, false><<<dim3(148, 4), 256, dsm>>>(
        down_w, nullptr, p_act, nullptr, out_x, nullptr, HID, INTER);
}

// round 11
// speedup vs baseline: 1.0120x; 1.0064x over previous
#include <cuda_runtime.h>
#include <math.h>
#include <cstdint>

#define HID   2048
#define INTER 8192
#define QKV   8192
#define TV    4096
#define NVH   32
#define KD    128
#define VD    128
#define NKH   16
#define PROJ_ROWS (QKV + TV + 2 * NVH)   // 12352

#define MODE_PLAIN  0
#define MODE_ATOMIC 1
#define MODE_GATEUP 2

#define NBUF 2
#define TILE_BYTES 16384
#define ROW_BYTES  8192

// ---- scratch ----
__device__ float g_proj[PROJ_ROWS];
__device__ float g_yg[TV];
__device__ float g_x1[HID];
__device__ float g_act[INTER];

__device__ __forceinline__ float warp_sum(float v) {
#pragma unroll
    for (int o = 16; o; o >>= 1) v += __shfl_xor_sync(0xffffffffu, v, o);
    return v;
}
__device__ __forceinline__ unsigned smem_u32(const void* p) {
    return (unsigned)__cvta_generic_to_shared(p);
}
__device__ __forceinline__ void mbar_init(unsigned a, unsigned cnt) {
    asm volatile("mbarrier.init.shared.b64 [%0], %1;" :: "r"(a), "r"(cnt) : "memory");
}
__device__ __forceinline__ void mbar_expect(unsigned a, unsigned bytes) {
    asm volatile("mbarrier.arrive.expect_tx.shared.b64 _, [%0], %1;"
                 :: "r"(a), "r"(bytes) : "memory");
}
__device__ __forceinline__ void bulk_g2s(unsigned dst, const void* src, unsigned bytes,
                                         unsigned mbar) {
    asm volatile("cp.async.bulk.shared::cta.global.mbarrier::complete_tx::bytes "
                 "[%0], [%1], %2, [%3];"
                 :: "r"(dst), "l"(src), "r"(bytes), "r"(mbar) : "memory");
}
__device__ __forceinline__ void bulk_g2s_ef(unsigned dst, const void* src, unsigned bytes,
                                            unsigned mbar) {
    uint64_t pol;
    asm("createpolicy.fractional.L2::evict_first.b64 %0, 1.0;" : "=l"(pol));
    asm volatile("cp.async.bulk.shared::cta.global.mbarrier::complete_tx::bytes"
                 ".L2::cache_hint [%0], [%1], %2, [%3], %4;"
                 :: "r"(dst), "l"(src), "r"(bytes), "r"(mbar), "l"(pol) : "memory");
}
__device__ __forceinline__ void mbar_wait(unsigned a, unsigned phase) {
    asm volatile("{\n\t"
                 ".reg .pred P;\n\t"
                 "WAIT_%=:\n\t"
                 "mbarrier.try_wait.parity.acquire.cta.shared::cta.b64 P, [%0], %1;\n\t"
                 "@P bra DONE_%=;\n\t"
                 "bra WAIT_%=;\n\t"
                 "DONE_%=:\n\t"
                 "}" :: "r"(a), "r"(phase) : "memory");
}
__device__ __forceinline__ void fence_async() {
    asm volatile("fence.proxy.async.shared::cta;" ::: "memory");
}
__device__ __forceinline__ void l2pf(const void* p) {
    asm volatile("prefetch.global.L2 [%0];" :: "l"(p));
}
// walk [base, base+bytes) in 128B lines, interleaved across pn prefetch blocks
__device__ void pf_range(const char* base, size_t bytes, int pidx, int pn) {
    if (!base || !bytes) return;
    size_t nl = bytes >> 7;
    for (size_t i = (size_t)pidx * blockDim.x + threadIdx.x; i < nl;
         i += (size_t)pn * blockDim.x)
        l2pf(base + (i << 7));
}

// ================= bulk-copy pipelined GEMV + next-stage L2 prefetch =================
// Compute blocks: blockIdx.x < gx_main (round-8 structure: NBUF=2, interleaved tiles).
// Prefetch blocks: blockIdx.x >= gx_main walk pf ranges with prefetch.global.L2.
// EF: tag streaming weight reads L2::evict_first (protect prefetched lines).
template <int KC, int MODE, bool LN, bool EF>
__global__ void __launch_bounds__(256)
gemv_bulk(const float* __restrict__ W, const float* __restrict__ W2,
          const float* __restrict__ xin, const float* __restrict__ lnw,
          float* __restrict__ outv, float* __restrict__ xcopy,
          int rows, int strideK, int gx_main,
          const char* pf1, size_t pb1, const char* pf2, size_t pb2,
          const char* pf3, size_t pb3) {
    if ((int)blockIdx.x >= gx_main) {
        const int npfx = gridDim.x - gx_main;
        const int pidx = (blockIdx.x - gx_main) + blockIdx.y * npfx;
        const int pn = npfx * gridDim.y;
        pf_range(pf1, pb1, pidx, pn);
        pf_range(pf2, pb2, pidx, pn);
        pf_range(pf3, pb3, pidx, pn);
        return;
    }
    extern __shared__ __align__(128) float4 dyn[];
    float4* sx4  = dyn;                    // KC/4 float4
    float4* bufb = dyn + KC / 4;           // NBUF * 1024 float4
    float* sx = reinterpret_cast<float*>(sx4);
    __shared__ float sacc[2][2][4];        // [parity][row][quarter]
    __shared__ float sred[9];
    __shared__ __align__(8) unsigned long long mbar[NBUF];
    const int tid = threadIdx.x;

    unsigned mb_u32[NBUF];
#pragma unroll
    for (int d = 0; d < NBUF; d++) mb_u32[d] = smem_u32(&mbar[d]);

    if (tid == 0) {
#pragma unroll
        for (int d = 0; d < NBUF; d++) mbar_init(mb_u32[d], 1);
        fence_async();
    }
    __syncthreads();

    // ---- stage x (optionally rmsnorm'd) ----
    if (LN) {
        float s = 0.f;
        bool cp = (xcopy != nullptr) && (blockIdx.x == 0) && (blockIdx.y == 0);
        for (int i = tid; i < KC; i += 256) {
            float v = xin[i];
            sx[i] = v;
            if (cp) xcopy[i] = v;
            s += v * v;
        }
        s = warp_sum(s);
        if ((tid & 31) == 0) sred[tid >> 5] = s;
        __syncthreads();
        if (tid < 32) {
            float v = (tid < 8) ? sred[tid] : 0.f;
            v = warp_sum(v);
            if (tid == 0) sred[8] = rsqrtf(v / (float)KC + 1e-6f);
        }
        __syncthreads();
        float inv = sred[8];
        for (int i = tid; i < KC; i += 256)
            sx[i] = sx[i] * inv * (1.f + lnw[i]);
        __syncthreads();
    } else {
        const float* xc = xin + (size_t)blockIdx.y * KC;
        for (int i = tid; i < KC; i += 256) sx[i] = xc[i];
        __syncthreads();
    }

    const size_t cb = (size_t)blockIdx.y * KC;
    const int gx = gx_main;
    const int NT = (MODE == MODE_GATEUP) ? rows : (rows >> 1);

    auto issue = [&](int T, int slot) {
        unsigned dst = smem_u32(&bufb[slot * 1024]);
        mbar_expect(mb_u32[slot], TILE_BYTES);
        const float* s0;
        const float* s1;
        if (MODE == MODE_GATEUP) {
            s0 = W  + (size_t)T * strideK;
            s1 = W2 + (size_t)T * strideK;
        } else {
            s0 = W + (size_t)(2 * T)     * strideK + cb;
            s1 = W + (size_t)(2 * T + 1) * strideK + cb;
        }
        if (EF) {
            bulk_g2s_ef(dst,             s0, ROW_BYTES, mb_u32[slot]);
            bulk_g2s_ef(dst + ROW_BYTES, s1, ROW_BYTES, mb_u32[slot]);
        } else {
            bulk_g2s(dst,             s0, ROW_BYTES, mb_u32[slot]);
            bulk_g2s(dst + ROW_BYTES, s1, ROW_BYTES, mb_u32[slot]);
        }
    };

    // prologue: fill the ring
    int Ti = blockIdx.x;
    if (tid == 0) {
#pragma unroll
        for (int d = 0; d < NBUF; d++) {
            if (Ti + d * gx < NT) issue(Ti + d * gx, d);
        }
    }
    Ti += NBUF * gx;

    const int w = tid >> 5, lane = tid & 31;
    const int rl = w >> 2, q = w & 3;
    float4 xr[4];
#pragma unroll
    for (int j = 0; j < 4; j++) xr[j] = sx4[q * (KC / 16) + j * 32 + lane];

    int it = 0;
    for (int Tc = blockIdx.x; Tc < NT; Tc += gx, it++) {
        const int slot = it % NBUF;
        const int ph = (it / NBUF) & 1;
        const int par = it & 1;
        mbar_wait(mb_u32[slot], ph);
        {
            const float4* src = &bufb[slot * 1024 + rl * 512];
            float acc = 0.f;
#pragma unroll
            for (int j = 0; j < 4; j++) {
                float4 wv = src[q * (KC / 16) + j * 32 + lane];
                acc += wv.x * xr[j].x + wv.y * xr[j].y + wv.z * xr[j].z + wv.w * xr[j].w;
            }
            acc = warp_sum(acc);
            if (lane == 0) sacc[par][rl][q] = acc;
        }
        __syncthreads();   // sacc visible; tile fully consumed
        if (tid == 0 && Ti < NT) issue(Ti, slot);
        Ti += gx;
        if (MODE == MODE_PLAIN) {
            if (tid < 2) {
                const float* a = sacc[par][tid];
                outv[2 * Tc + tid] = a[0] + a[1] + a[2] + a[3];
            }
        } else if (MODE == MODE_ATOMIC) {
            if (tid < 2) {
                const float* a = sacc[par][tid];
                atomicAdd(&outv[2 * Tc + tid], a[0] + a[1] + a[2] + a[3]);
            }
        } else {
            if (tid == 0) {
                const float* a0 = sacc[par][0];
                const float* a1 = sacc[par][1];
                float ag = a0[0] + a0[1] + a0[2] + a0[3];
                float au = a1[0] + a1[1] + a1[2] + a1[3];
                float silu = ag / (1.f + expf(-ag));
                outv[Tc] = silu * au;
            }
        }
    }
}

// ================= gated delta rule with fused conv update (+ prefetch blocks) =================
__global__ void __launch_bounds__(1024, 1)
delta_k(const float* __restrict__ S, const float* __restrict__ proj,
        const float* __restrict__ cs, const float* __restrict__ cw,
        const float* __restrict__ A_log, const float* __restrict__ dt_bias,
        const float* __restrict__ norm_w,
        float* __restrict__ Sout, float* __restrict__ out_cs, float* __restrict__ yg,
        const char* pf1, size_t pb1, const char* pf2, size_t pb2) {
    if ((int)blockIdx.x >= NVH) {
        const int pidx = blockIdx.x - NVH;
        const int pn = gridDim.x - NVH;
        pf_range(pf1, pb1, pidx, pn);
        pf_range(pf2, pb2, pidx, pn);
        return;
    }
    __shared__ float sq[KD], sk[KD], sv[VD], sdelta[VD], sred[8];
    __shared__ float spart[8][VD];
    int h = blockIdx.x;
    int tid = threadIdx.x;
    int t = tid & (VD - 1);
    int p = tid >> 7;
    int kh = h >> 1;

    if (tid < 384) {
        int row;
        if (tid < 128)      row = kh * KD + tid;
        else if (tid < 256) row = NKH * KD + kh * KD + (tid - 128);
        else                row = 2 * NKH * KD + h * VD + (tid - 256);
        float4 c = __ldg(reinterpret_cast<const float4*>(cs) + row);
        float4 w = __ldg(reinterpret_cast<const float4*>(cw) + row);
        float qv = proj[row];
        float s = c.y * w.x + c.z * w.y + c.w * w.z + qv * w.w;
        float act = s / (1.f + expf(-s));
        if (tid < 128)      sq[tid] = act;
        else if (tid < 256) sk[tid - 128] = act;
        else                sv[tid - 256] = act;
        if (tid >= 256 || (h & 1) == 0)
            reinterpret_cast<float4*>(out_cs)[row] = make_float4(c.y, c.z, c.w, qv);
    }
    __syncthreads();

    if (tid < 256) {
        float v = (tid < 128) ? sq[tid] : sk[tid - 128];
        float ss = warp_sum(v * v);
        if ((tid & 31) == 0) sred[tid >> 5] = ss;
    }
    __syncthreads();
    float sumq = sred[0] + sred[1] + sred[2] + sred[3];
    float sumk = sred[4] + sred[5] + sred[6] + sred[7];
    float inq = 1.f / fmaxf(sqrtf(sumq), 1e-12f);
    float ink = 1.f / fmaxf(sqrtf(sumk), 1e-12f);

    float a = proj[QKV + TV + h];
    float bb = proj[QKV + TV + NVH + h];
    float beta = 1.f / (1.f + expf(-bb));
    float xsp = a + dt_bias[h];
    float sp = (xsp > 20.f) ? xsp : log1pf(expf(xsp));
    float decay = expf(-expf(A_log[h]) * sp);

    const float* Sh = S + (size_t)h * KD * VD;
    float* So = Sout + (size_t)h * KD * VD;

    float Sreg[16];
    float acc = 0.f;
#pragma unroll
    for (int j = 0; j < 16; j++) {
        int k = p * 16 + j;
        Sreg[j] = Sh[k * VD + t];
        acc += Sreg[j] * sk[k];
    }
    spart[p][t] = acc * ink;
    __syncthreads();
    if (p == 0) {
        float s = 0.f;
#pragma unroll
        for (int j = 0; j < 8; j++) s += spart[j][t];
        sdelta[t] = sv[t] - s;
    }
    __syncthreads();

    float d = sdelta[t];
    float yacc = 0.f;
#pragma unroll
    for (int j = 0; j < 16; j++) {
        int k = p * 16 + j;
        float ns = decay * Sreg[j] + beta * (sk[k] * ink) * d;
        So[k * VD + t] = ns;
        yacc += ns * sq[k];
    }
    spart[p][t] = yacc * inq;
    __syncthreads();

    float y = 0.f;
    if (tid < VD) {
#pragma unroll
        for (int j = 0; j < 8; j++) y += spart[j][tid];
        float vy = warp_sum(y * y);
        if ((tid & 31) == 0) sred[tid >> 5] = vy;
    }
    __syncthreads();
    if (tid < VD) {
        float sumy = sred[0] + sred[1] + sred[2] + sred[3];
        float yn = y * rsqrtf(sumy / (float)VD + 1e-6f) * norm_w[tid];
        float z = proj[QKV + h * VD + tid];
        yg[h * VD + tid] = yn * (z / (1.f + expf(-z)));
    }
}

extern "C" void kernel_launch(void* const* d_in, const int* in_sizes, int n_in,
                              void* d_out, int out_size) {
    const float* x          = (const float*)d_in[0];
    const float* conv_state = (const float*)d_in[1];
    const float* ssm_state  = (const float*)d_in[2];
    const float* in_ln_w    = (const float*)d_in[3];
    const float* in_proj_w  = (const float*)d_in[4];
    const float* conv_w     = (const float*)d_in[5];
    const float* A_log      = (const float*)d_in[6];
    const float* dt_bias    = (const float*)d_in[7];
    const float* norm_w     = (const float*)d_in[8];
    const float* out_proj_w = (const float*)d_in[9];
    const float* post_ln_w  = (const float*)d_in[10];
    const float* gate_w     = (const float*)d_in[11];
    const float* up_w       = (const float*)d_in[12];
    const float* down_w     = (const float*)d_in[13];

    float* out = (float*)d_out;
    float* out_x    = out;
    float* out_conv = out + HID;
    float* out_ssm  = out + HID + QKV * 4;

    float *p_proj, *p_yg, *p_x1, *p_act;
    cudaGetSymbolAddress((void**)&p_proj, g_proj);
    cudaGetSymbolAddress((void**)&p_yg,   g_yg);
    cudaGetSymbolAddress((void**)&p_x1,   g_x1);
    cudaGetSymbolAddress((void**)&p_act,  g_act);

    const size_t dsm = (size_t)(HID / 4 + NBUF * 1024) * sizeof(float4);  // 40KB

    const size_t RB = ROW_BYTES;                  // 8KB per weight row
    const char* cgate = (const char*)gate_w;
    const char* cup   = (const char*)up_w;

    // 1. in_proj (fused rmsnorm; block0 seeds x1=x); prefetch out_proj + gate/up[0:2560)
    gemv_bulk<HID, MODE_PLAIN, true, true><<<740, 256, dsm>>>(
        in_proj_w, nullptr, x, in_ln_w, p_proj, p_x1, PROJ_ROWS, HID, 592,
        (const char*)out_proj_w, (size_t)TV * HID * 4,
        cgate, 2560 * RB, cup, 2560 * RB);
    // 2. delta rule + conv; prefetch gate/up[2560:4608)
    delta_k<<<NVH + 148, 1024>>>(ssm_state, p_proj, conv_state, conv_w,
        A_log, dt_bias, norm_w, out_ssm, out_conv, p_yg,
        cgate + 2560 * RB, 2048 * RB, cup + 2560 * RB, 2048 * RB);
    // 3. out_proj split-2 (atomics onto x1); prefetch gate/up[4608:6656)
    gemv_bulk<HID, MODE_ATOMIC, false, false><<<dim3(370, 2), 256, dsm>>>(
        out_proj_w, nullptr, p_yg, nullptr, p_x1, nullptr, HID, TV, 296,
        cgate + 4608 * RB, 2048 * RB, cup + 4608 * RB, 2048 * RB, nullptr, 0);
    // 4. post-rmsnorm + gate/up + SwiGLU (block0 seeds out_x=x1); prefetch down (67MB)
    gemv_bulk<HID, MODE_GATEUP, true, true><<<740, 256, dsm>>>(
        gate_w, up_w, p_x1, post_ln_w, p_act, out_x, INTER, HID, 592,
        (const char*)down_w, (size_t)HID * INTER * 4, nullptr, 0, nullptr, 0);
    // 5. down split-4, atomics onto out_x
    gemv_bulk<HID, MODE_ATOMIC, false, false><<<dim3(148, 4), 256, dsm>>>(
        down_w, nullptr, p_act, nullptr, out_x, nullptr, HID, INTER, 148,
        nullptr, 0, nullptr, 0, nullptr, 0);
}